// round 13
// baseline (speedup 1.0000x reference)
#include <cuda_runtime.h>
#include <cuda_bf16.h>

// ---------------------------------------------------------------------------
// Static geometry:
//   s0: t=8,  32x32 -> tokens [0,8192)      pe2d rows [0,1024)
//   s1: t=16, 16x16 -> tokens [8192,12288)  pe2d rows [1024,1280)
//   s2: t=4,  48x48 -> tokens [12288,21504) pe2d rows [1280,3584)
//   s3: t=1,  64x64 -> tokens [21504,25600) pe = weight rows directly
// Resize rows (axes symmetric): g 0..31: 64->32, 32..47: 64->16, 48..95: 64->48
// ---------------------------------------------------------------------------
#define DIM      1280
#define D4       320
#define NROWS_W  96
#define PE_ROWS  3584
#define TOKENS   25600

__device__ float g_tmpW[64 * NROWS_W * DIM];   // [i][c][d]
__device__ float g_pe2d[PE_ROWS * DIM];

// ---------------------------------------------------------------------------
// Compile-time tap-window geometry (integer-exact; matches ceil(f - 2*inv_scale))
//   outsz=32: inv=2,   f=2r+0.5   -> lo = 2r-3            width 8
//   outsz=16: inv=4,   f=4r+1.5   -> lo = 4r-6            width 16
//   outsz=48: inv=4/3, f=(8r+1)/6 -> lo = ceil((8r-15)/6) width 6
// start clamped to [0, 64-width]; taps outside [0,64) masked BEFORE wsum.
// ---------------------------------------------------------------------------
__host__ __device__ constexpr int cdiv_ceil(int n, int d) {
    return (n >= 0) ? (n + d - 1) / d : -((-n) / d);
}
__host__ __device__ constexpr int iclamp(int v, int lo, int hi) {
    return v < lo ? lo : (v > hi ? hi : v);
}
__host__ __device__ constexpr int rowStart(int g) {
    return (g < 32) ? iclamp(2 * g - 3, 0, 56)
         : (g < 48) ? iclamp(4 * (g - 32) - 6, 0, 48)
                    : iclamp(cdiv_ceil(8 * (g - 48) - 15, 6), 0, 58);
}
__host__ __device__ constexpr int rowWidth(int g) {
    return (g < 32) ? 8 : (g < 48) ? 16 : 6;
}

// ---------------------------------------------------------------------------
// Compile-time weight table: exact fp64 Keys-cubic (a=-0.5), antialiased,
// column-normalized over valid taps only (same math as the R8 init kernel).
// ---------------------------------------------------------------------------
constexpr double c_abs(double x) { return x < 0.0 ? -x : x; }
constexpr double keys_cubic_c(double x) {
    return (x >= 2.0) ? 0.0
         : (x >= 1.0) ? ((-0.5 * x + 2.5) * x - 4.0) * x + 2.0
                      : ((1.5 * x - 2.5) * x) * x + 1.0;
}

struct WTable { float w[NROWS_W][16]; };

constexpr WTable make_wtable() {
    WTable t{};
    for (int o = 0; o < NROWS_W; o++) {
        int outsz = (o < 32) ? 32 : (o < 48) ? 16 : 48;
        int base  = (o < 32) ? 0  : (o < 48) ? 32 : 48;
        int r = o - base;
        double inv_scale = 64.0 / (double)outsz;          // == kernel_scale
        double ks_inv    = (double)outsz * (1.0 / 64.0);  // 1/kernel_scale
        double f = ((double)r + 0.5) * inv_scale - 0.5;
        int start = rowStart(o);
        double wv[16] = {};
        double wsum = 0.0;
        for (int k = 0; k < 16; k++) {
            int i = start + k;
            double w = (i < 64) ? keys_cubic_c(c_abs(f - (double)i) * ks_inv) : 0.0;
            wv[k] = w;
            wsum += w;
        }
        for (int k = 0; k < 16; k++)
            t.w[o][k] = (float)(wv[k] / wsum);
    }
    return t;
}

constexpr WTable WT = make_wtable();

// ---------------------------------------------------------------------------
// Template-unrolled emitters (R11-proven): data in registers, weights as
// FFMA immediates. C++14-safe recursion.
// ---------------------------------------------------------------------------
template<int G, int K, bool Done>
struct Tap {
    static __device__ __forceinline__ float run(const float (&v)[64], float acc) {
        constexpr float wk = WT.w[G][K];
        constexpr int   st = rowStart(G);
        acc = fmaf(wk, v[st + K], acc);
        return Tap<G, K + 1, (K + 1 >= rowWidth(G))>::run(v, acc);
    }
};
template<int G, int K>
struct Tap<G, K, true> {
    static __device__ __forceinline__ float run(const float (&)[64], float acc) { return acc; }
};

template<int C, bool Done>
struct WCol {
    static __device__ __forceinline__ void run(const float (&v)[64],
                                               float* __restrict__ outp) {
        outp[(size_t)C * DIM] = Tap<C, 0, false>::run(v, 0.f);
        WCol<C + 1, (C + 1 >= NROWS_W)>::run(v, outp);
    }
};
template<int C>
struct WCol<C, true> {
    static __device__ __forceinline__ void run(const float (&)[64], float*) {}
};

template<int GBASE, int RCNT, int WS, int R, bool Done>
struct HRow {
    static __device__ __forceinline__ void run(const float (&v)[64],
                                               float* __restrict__ outp) {
        outp[(size_t)(R * WS) * DIM] = Tap<GBASE + R, 0, false>::run(v, 0.f);
        HRow<GBASE, RCNT, WS, R + 1, (R + 1 >= RCNT)>::run(v, outp);
    }
};
template<int GBASE, int RCNT, int WS, int R>
struct HRow<GBASE, RCNT, WS, R, true> {
    static __device__ __forceinline__ void run(const float (&)[64], float*) {}
};

// ---------------------------------------------------------------------------
// Kernel 1 (W-pass): tmpW[i][c][d] = sum_k W[c][k] * weight[i][st_c+k][d]
// Block = (input row i, 128-float d-chunk). R11-proven form.
// ---------------------------------------------------------------------------
__global__ __launch_bounds__(128) void passW_kernel(const float* __restrict__ weight) {
    int i  = blockIdx.x;
    int d0 = blockIdx.y * 128;
    int tid = threadIdx.x;

    float v[64];
    const float* wrow = weight + (size_t)(i * 64) * DIM + d0 + tid;
    #pragma unroll
    for (int j = 0; j < 64; j++)
        v[j] = wrow[(size_t)j * DIM];

    float* outp = g_tmpW + (size_t)i * NROWS_W * DIM + d0 + tid;
    WCol<0, false>::run(v, outp);
}

// ---------------------------------------------------------------------------
// Kernel 2 (H-pass): pe2d[row(s,r,c)][d] = sum_k W[r][k] * tmpW[st_r+k][c][d]
// Block = (global resized column c, d-chunk). R11-proven form.
// ---------------------------------------------------------------------------
__global__ __launch_bounds__(128) void passH_kernel() {
    int c  = blockIdx.x;
    int d0 = blockIdx.y * 128;
    int tid = threadIdx.x;

    float v[64];
    const float* src = g_tmpW + (size_t)c * DIM + d0 + tid;
    #pragma unroll
    for (int i = 0; i < 64; i++)
        v[i] = src[(size_t)i * (NROWS_W * DIM)];

    if (c < 32) {
        float* outp = g_pe2d + (size_t)c * DIM + d0 + tid;
        HRow<0, 32, 32, 0, false>::run(v, outp);
    } else if (c < 48) {
        float* outp = g_pe2d + (size_t)(1024 + (c - 32)) * DIM + d0 + tid;
        HRow<32, 16, 16, 0, false>::run(v, outp);
    } else {
        float* outp = g_pe2d + (size_t)(1280 + (c - 48)) * DIM + d0 + tid;
        HRow<48, 48, 48, 0, false>::run(v, outp);
    }
}

// ---------------------------------------------------------------------------
// Kernel 3 (NEW): block = one pe2d row x ALL t frames of its sample.
// pe is loaded from L2 ONCE per block (was once per frame): pe L2 traffic
// drops 128 MB -> 39 MB. tw is tiny and L1-resident. x/out stay coalesced.
//   blocks [0,1024):    s0 row r, frames f=0..7,  token = f*1024 + r
//   blocks [1024,1280): s1 row r, frames f=0..15, token = 8192 + f*256 + r
//   blocks [1280,3584): s2 row r, frames f=0..3,  token = 12288 + f*2304 + r
//   blocks [3584,4608): s3 identity, 4 consecutive tokens (pe = weight rows)
// ---------------------------------------------------------------------------
__global__ __launch_bounds__(320) void add_kernel(const float4* __restrict__ x,
                                                  const float4* __restrict__ weight,
                                                  const float4* __restrict__ tw,
                                                  float4* __restrict__ out) {
    int b  = blockIdx.x;
    int d4 = threadIdx.x;

    if (b < 1024) {                              // s0: t=8, hw=1024
        float4 pe = ((const float4*)g_pe2d)[(size_t)b * D4 + d4];
        #pragma unroll
        for (int f = 0; f < 8; f++) {
            size_t idx = (size_t)(f * 1024 + b) * D4 + d4;
            float4 a = __ldcs(&x[idx]);
            float4 t = tw[(size_t)f * D4 + d4];
            float4 r;
            r.x = a.x + pe.x + t.x; r.y = a.y + pe.y + t.y;
            r.z = a.z + pe.z + t.z; r.w = a.w + pe.w + t.w;
            __stcs(&out[idx], r);
        }
    } else if (b < 1280) {                       // s1: t=16, hw=256
        int rrow = b - 1024;
        float4 pe = ((const float4*)g_pe2d)[(size_t)(1024 + rrow) * D4 + d4];
        #pragma unroll
        for (int f = 0; f < 16; f++) {
            size_t idx = (size_t)(8192 + f * 256 + rrow) * D4 + d4;
            float4 a = __ldcs(&x[idx]);
            float4 t = tw[(size_t)f * D4 + d4];
            float4 r;
            r.x = a.x + pe.x + t.x; r.y = a.y + pe.y + t.y;
            r.z = a.z + pe.z + t.z; r.w = a.w + pe.w + t.w;
            __stcs(&out[idx], r);
        }
    } else if (b < 3584) {                       // s2: t=4, hw=2304
        int rrow = b - 1280;
        float4 pe = ((const float4*)g_pe2d)[(size_t)(1280 + rrow) * D4 + d4];
        #pragma unroll
        for (int f = 0; f < 4; f++) {
            size_t idx = (size_t)(12288 + f * 2304 + rrow) * D4 + d4;
            float4 a = __ldcs(&x[idx]);
            float4 t = tw[(size_t)f * D4 + d4];
            float4 r;
            r.x = a.x + pe.x + t.x; r.y = a.y + pe.y + t.y;
            r.z = a.z + pe.z + t.z; r.w = a.w + pe.w + t.w;
            __stcs(&out[idx], r);
        }
    } else {                                     // s3: t=1, identity; 4 tokens/block
        int u = (b - 3584) * 4;
        #pragma unroll
        for (int j = 0; j < 4; j++) {
            size_t idx = (size_t)(21504 + u + j) * D4 + d4;
            float4 a  = __ldcs(&x[idx]);
            float4 pe = weight[(size_t)(u + j) * D4 + d4];
            float4 r;
            r.x = a.x + pe.x; r.y = a.y + pe.y;
            r.z = a.z + pe.z; r.w = a.w + pe.w;
            __stcs(&out[idx], r);
        }
    }
}

// ---------------------------------------------------------------------------
extern "C" void kernel_launch(void* const* d_in, const int* in_sizes, int n_in,
                              void* d_out, int out_size) {
    const float* x      = (const float*)d_in[0];
    const float* weight = (const float*)d_in[1];
    const float* tw     = (const float*)d_in[2];
    float* out = (float*)d_out;

    passW_kernel<<<dim3(64, 10), 128>>>(weight);
    passH_kernel<<<dim3(96, 10), 128>>>();
    add_kernel<<<4608, 320>>>((const float4*)x, (const float4*)weight,
                              (const float4*)tw, (float4*)out);
}

// round 14
// speedup vs baseline: 1.0278x; 1.0278x over previous
#include <cuda_runtime.h>
#include <cuda_bf16.h>

// ---------------------------------------------------------------------------
// Static geometry:
//   s0: t=8,  32x32 -> tokens [0,8192)      pe2d rows [0,1024)
//   s1: t=16, 16x16 -> tokens [8192,12288)  pe2d rows [1024,1280)
//   s2: t=4,  48x48 -> tokens [12288,21504) pe2d rows [1280,3584)
//   s3: t=1,  64x64 -> tokens [21504,25600) pe = weight rows directly
// Resize rows (axes symmetric): g 0..31: 64->32, 32..47: 64->16, 48..95: 64->48
// ---------------------------------------------------------------------------
#define DIM      1280
#define D4       320
#define NROWS_W  96
#define PE_ROWS  3584
#define TOKENS   25600
#define TPB      4          // tokens per add-block (all boundaries divisible by 4)
#define BAND     40         // every tap window fits in a 40-row band

__device__ float g_tmpW[64 * NROWS_W * DIM];   // [i][c][d]
__device__ float g_pe2d[PE_ROWS * DIM];

// ---------------------------------------------------------------------------
// Compile-time tap-window geometry (integer-exact; matches ceil(f - 2*inv_scale))
//   outsz=32: inv=2,   f=2r+0.5   -> lo = 2r-3            width 8
//   outsz=16: inv=4,   f=4r+1.5   -> lo = 4r-6            width 16
//   outsz=48: inv=4/3, f=(8r+1)/6 -> lo = ceil((8r-15)/6) width 6
// start clamped to [0, 64-width]; taps outside [0,64) masked BEFORE wsum.
// ---------------------------------------------------------------------------
__host__ __device__ constexpr int cdiv_ceil(int n, int d) {
    return (n >= 0) ? (n + d - 1) / d : -((-n) / d);
}
__host__ __device__ constexpr int iclamp(int v, int lo, int hi) {
    return v < lo ? lo : (v > hi ? hi : v);
}
__host__ __device__ constexpr int rowStart(int g) {
    return (g < 32) ? iclamp(2 * g - 3, 0, 56)
         : (g < 48) ? iclamp(4 * (g - 32) - 6, 0, 48)
                    : iclamp(cdiv_ceil(8 * (g - 48) - 15, 6), 0, 58);
}
__host__ __device__ constexpr int rowWidth(int g) {
    return (g < 32) ? 8 : (g < 48) ? 16 : 6;
}
// Band split (within one block): group 0 = rows with start<=24 (band [0,40)),
// group 1 = start>=25 (band [24,64)). Window (width<=16) always fits its band.
__host__ __device__ constexpr bool inGroup(int g, int z) {
    return z == 0 ? (rowStart(g) <= 24) : (rowStart(g) >= 25);
}
__host__ __device__ constexpr int bandBase(int z) { return z * 24; }

// ---------------------------------------------------------------------------
// Compile-time weight table: exact fp64 Keys-cubic (a=-0.5), antialiased,
// column-normalized over valid taps only (same math as the R8 init kernel).
// ---------------------------------------------------------------------------
constexpr double c_abs(double x) { return x < 0.0 ? -x : x; }
constexpr double keys_cubic_c(double x) {
    return (x >= 2.0) ? 0.0
         : (x >= 1.0) ? ((-0.5 * x + 2.5) * x - 4.0) * x + 2.0
                      : ((1.5 * x - 2.5) * x) * x + 1.0;
}

struct WTable { float w[NROWS_W][16]; };

constexpr WTable make_wtable() {
    WTable t{};
    for (int o = 0; o < NROWS_W; o++) {
        int outsz = (o < 32) ? 32 : (o < 48) ? 16 : 48;
        int base  = (o < 32) ? 0  : (o < 48) ? 32 : 48;
        int r = o - base;
        double inv_scale = 64.0 / (double)outsz;          // == kernel_scale
        double ks_inv    = (double)outsz * (1.0 / 64.0);  // 1/kernel_scale
        double f = ((double)r + 0.5) * inv_scale - 0.5;
        int start = rowStart(o);
        double wv[16] = {};
        double wsum = 0.0;
        for (int k = 0; k < 16; k++) {
            int i = start + k;
            double w = (i < 64) ? keys_cubic_c(c_abs(f - (double)i) * ks_inv) : 0.0;
            wv[k] = w;
            wsum += w;
        }
        for (int k = 0; k < 16; k++)
            t.w[o][k] = (float)(wv[k] / wsum);
    }
    return t;
}

constexpr WTable WT = make_wtable();

// ---------------------------------------------------------------------------
// Template-unrolled emitters over a 40-float band; weights are immediates.
// (Correctness proven in R12; now used with both groups in ONE block.)
// ---------------------------------------------------------------------------
template<int G, int K, int BASE, bool Done>
struct TapB {
    static __device__ __forceinline__ float run(const float (&v)[BAND], float acc) {
        constexpr float wk = WT.w[G][K];
        constexpr int   ix = rowStart(G) - BASE + K;
        acc = fmaf(wk, v[ix], acc);
        return TapB<G, K + 1, BASE, (K + 1 >= rowWidth(G))>::run(v, acc);
    }
};
template<int G, int K, int BASE>
struct TapB<G, K, BASE, true> {
    static __device__ __forceinline__ float run(const float (&)[BAND], float acc) { return acc; }
};

// ---- W-pass: emit column C at outp[C*DIM] if C is in group Z ----
template<int C, int Z, bool DoEmit>
struct WEmit {
    static __device__ __forceinline__ void run(const float (&v)[BAND],
                                               float* __restrict__ outp) {
        outp[(size_t)C * DIM] = TapB<C, 0, bandBase(Z), false>::run(v, 0.f);
    }
};
template<int C, int Z>
struct WEmit<C, Z, false> {
    static __device__ __forceinline__ void run(const float (&)[BAND], float*) {}
};

template<int C, int Z, bool Done>
struct WColZ {
    static __device__ __forceinline__ void run(const float (&v)[BAND],
                                               float* __restrict__ outp) {
        WEmit<C, Z, inGroup(C, Z)>::run(v, outp);
        WColZ<C + 1, Z, (C + 1 >= NROWS_W)>::run(v, outp);
    }
};
template<int C, int Z>
struct WColZ<C, Z, true> {
    static __device__ __forceinline__ void run(const float (&)[BAND], float*) {}
};

// ---- H-pass: emit local row R (global g=GBASE+R) at outp[R*WS*DIM] if in group Z ----
template<int GBASE, int WS, int R, int Z, bool DoEmit>
struct HEmit {
    static __device__ __forceinline__ void run(const float (&v)[BAND],
                                               float* __restrict__ outp) {
        outp[(size_t)(R * WS) * DIM] = TapB<GBASE + R, 0, bandBase(Z), false>::run(v, 0.f);
    }
};
template<int GBASE, int WS, int R, int Z>
struct HEmit<GBASE, WS, R, Z, false> {
    static __device__ __forceinline__ void run(const float (&)[BAND], float*) {}
};

template<int GBASE, int RCNT, int WS, int R, int Z, bool Done>
struct HRowZ {
    static __device__ __forceinline__ void run(const float (&v)[BAND],
                                               float* __restrict__ outp) {
        HEmit<GBASE, WS, R, Z, inGroup(GBASE + R, Z)>::run(v, outp);
        HRowZ<GBASE, RCNT, WS, R + 1, Z, (R + 1 >= RCNT)>::run(v, outp);
    }
};
template<int GBASE, int RCNT, int WS, int R, int Z>
struct HRowZ<GBASE, RCNT, WS, R, Z, true> {
    static __device__ __forceinline__ void run(const float (&)[BAND], float*) {}
};

// ---------------------------------------------------------------------------
// Kernel 1 (W-pass): tmpW[i][c][d] = sum_k W[c][k] * weight[i][st_c+k][d]
// Block = (input row i, 128-float d-chunk), 256 threads: lanes 0-127 compute
// group-0 columns from band rows [0,40); lanes 128-255 group-1 from [24,64).
// Overlap rows are fetched by the SAME SM (L1/L2 hit) -> no extra DRAM
// traffic, but 2x threads vs R11 -> occupancy cap 27% -> 54%.
// ---------------------------------------------------------------------------
__global__ __launch_bounds__(256) void passW_kernel(const float* __restrict__ weight) {
    int i  = blockIdx.x;
    int d0 = blockIdx.y * 128;
    int tid = threadIdx.x & 127;
    int z   = threadIdx.x >> 7;

    float v[BAND];
    const float* wrow = weight + (size_t)(i * 64 + z * 24) * DIM + d0 + tid;
    #pragma unroll
    for (int j = 0; j < BAND; j++)
        v[j] = wrow[(size_t)j * DIM];

    float* outp = g_tmpW + (size_t)i * NROWS_W * DIM + d0 + tid;
    if (z == 0) WColZ<0, 0, false>::run(v, outp);
    else        WColZ<0, 1, false>::run(v, outp);
}

// ---------------------------------------------------------------------------
// Kernel 2 (H-pass): pe2d[row(s,r,c)][d] = sum_k W[r][k] * tmpW[st_r+k][c][d]
// Same within-block band split as passW.
// ---------------------------------------------------------------------------
__global__ __launch_bounds__(256) void passH_kernel() {
    int c  = blockIdx.x;
    int d0 = blockIdx.y * 128;
    int tid = threadIdx.x & 127;
    int z   = threadIdx.x >> 7;

    float v[BAND];
    const float* src = g_tmpW + (size_t)c * DIM
                     + (size_t)(z * 24) * (NROWS_W * DIM) + d0 + tid;
    #pragma unroll
    for (int i = 0; i < BAND; i++)
        v[i] = src[(size_t)i * (NROWS_W * DIM)];

    if (c < 32) {
        float* outp = g_pe2d + (size_t)c * DIM + d0 + tid;
        if (z == 0) HRowZ<0, 32, 32, 0, 0, false>::run(v, outp);
        else        HRowZ<0, 32, 32, 0, 1, false>::run(v, outp);
    } else if (c < 48) {
        float* outp = g_pe2d + (size_t)(1024 + (c - 32)) * DIM + d0 + tid;
        if (z == 0) HRowZ<32, 16, 16, 0, 0, false>::run(v, outp);
        else        HRowZ<32, 16, 16, 0, 1, false>::run(v, outp);
    } else {
        float* outp = g_pe2d + (size_t)(1280 + (c - 48)) * DIM + d0 + tid;
        if (z == 0) HRowZ<48, 48, 48, 0, 0, false>::run(v, outp);
        else        HRowZ<48, 48, 48, 0, 1, false>::run(v, outp);
    }
}

// ---------------------------------------------------------------------------
// Kernel 3 (R11-proven best): out = x + pe(+tw). Block = 4 consecutive
// tokens x 320 threads. Sample/frame/tw-row are block-uniform; pe rows
// consecutive; tw reused 4x; 4-deep MLP on the x stream.
// ---------------------------------------------------------------------------
__global__ __launch_bounds__(320) void add_kernel(const float4* __restrict__ x,
                                                  const float4* __restrict__ weight,
                                                  const float4* __restrict__ tw,
                                                  float4* __restrict__ out) {
    int t0 = blockIdx.x * TPB;
    int d4 = threadIdx.x;

    const float4* pe0;
    int frame;
    if (t0 < 8192) {                        // s0: t=8, 32x32
        frame = t0 >> 10;
        pe0 = (const float4*)g_pe2d + (size_t)(t0 & 1023) * D4;
    } else if (t0 < 12288) {                // s1: t=16, 16x16
        int u = t0 - 8192;
        frame = u >> 8;
        pe0 = (const float4*)g_pe2d + (size_t)(1024 + (u & 255)) * D4;
    } else if (t0 < 21504) {                // s2: t=4, 48x48
        int u = t0 - 12288;
        frame = u / 2304;
        pe0 = (const float4*)g_pe2d + (size_t)(1280 + (u - frame * 2304)) * D4;
    } else {                                // s3: t=1, identity 64x64
        frame = -1;
        pe0 = weight + (size_t)(t0 - 21504) * D4;
    }

    size_t base = (size_t)t0 * D4 + d4;

    float4 a[TPB], b[TPB];
    #pragma unroll
    for (int j = 0; j < TPB; j++) a[j] = __ldcs(&x[base + (size_t)j * D4]);
    #pragma unroll
    for (int j = 0; j < TPB; j++) b[j] = pe0[(size_t)j * D4 + d4];

    float4 t = make_float4(0.f, 0.f, 0.f, 0.f);
    if (frame >= 0) t = tw[(size_t)frame * D4 + d4];

    #pragma unroll
    for (int j = 0; j < TPB; j++) {
        float4 r;
        r.x = a[j].x + b[j].x + t.x;
        r.y = a[j].y + b[j].y + t.y;
        r.z = a[j].z + b[j].z + t.z;
        r.w = a[j].w + b[j].w + t.w;
        __stcs(&out[base + (size_t)j * D4], r);
    }
}

// ---------------------------------------------------------------------------
extern "C" void kernel_launch(void* const* d_in, const int* in_sizes, int n_in,
                              void* d_out, int out_size) {
    const float* x      = (const float*)d_in[0];
    const float* weight = (const float*)d_in[1];
    const float* tw     = (const float*)d_in[2];
    float* out = (float*)d_out;

    passW_kernel<<<dim3(64, 10), 256>>>(weight);
    passH_kernel<<<dim3(96, 10), 256>>>();
    add_kernel<<<TOKENS / TPB, 320>>>((const float4*)x, (const float4*)weight,
                                      (const float4*)tw, (float4*)out);
}

// round 15
// speedup vs baseline: 1.0283x; 1.0005x over previous
#include <cuda_runtime.h>
#include <cuda_bf16.h>

// ---------------------------------------------------------------------------
// Static geometry:
//   s0: t=8,  32x32 -> tokens [0,8192)      pe2d rows [0,1024)
//   s1: t=16, 16x16 -> tokens [8192,12288)  pe2d rows [1024,1280)
//   s2: t=4,  48x48 -> tokens [12288,21504) pe2d rows [1280,3584)
//   s3: t=1,  64x64 -> tokens [21504,25600) pe = weight rows (independent of prep!)
// Resize rows (axes symmetric): g 0..31: 64->32, 32..47: 64->16, 48..95: 64->48
// ---------------------------------------------------------------------------
#define DIM      1280
#define D4       320
#define NROWS_W  96
#define PE_ROWS  3584
#define TOKENS   25600
#define TPB      4          // tokens per add-block
#define BAND     40         // every tap window fits in a 40-row band

__device__ float g_tmpW[64 * NROWS_W * DIM];   // [i][c][d]
__device__ float g_pe2d[PE_ROWS * DIM];

// ---------------------------------------------------------------------------
// Compile-time tap-window geometry (integer-exact; matches ceil(f - 2*inv_scale))
// ---------------------------------------------------------------------------
__host__ __device__ constexpr int cdiv_ceil(int n, int d) {
    return (n >= 0) ? (n + d - 1) / d : -((-n) / d);
}
__host__ __device__ constexpr int iclamp(int v, int lo, int hi) {
    return v < lo ? lo : (v > hi ? hi : v);
}
__host__ __device__ constexpr int rowStart(int g) {
    return (g < 32) ? iclamp(2 * g - 3, 0, 56)
         : (g < 48) ? iclamp(4 * (g - 32) - 6, 0, 48)
                    : iclamp(cdiv_ceil(8 * (g - 48) - 15, 6), 0, 58);
}
__host__ __device__ constexpr int rowWidth(int g) {
    return (g < 32) ? 8 : (g < 48) ? 16 : 6;
}
// Band split (used by passH only; passW measured better without it)
__host__ __device__ constexpr bool inGroup(int g, int z) {
    return z == 0 ? (rowStart(g) <= 24) : (rowStart(g) >= 25);
}
__host__ __device__ constexpr int bandBase(int z) { return z * 24; }

// ---------------------------------------------------------------------------
// Compile-time weight table: exact fp64 Keys-cubic (a=-0.5), antialiased,
// column-normalized over valid taps only.
// ---------------------------------------------------------------------------
constexpr double c_abs(double x) { return x < 0.0 ? -x : x; }
constexpr double keys_cubic_c(double x) {
    return (x >= 2.0) ? 0.0
         : (x >= 1.0) ? ((-0.5 * x + 2.5) * x - 4.0) * x + 2.0
                      : ((1.5 * x - 2.5) * x) * x + 1.0;
}

struct WTable { float w[NROWS_W][16]; };

constexpr WTable make_wtable() {
    WTable t{};
    for (int o = 0; o < NROWS_W; o++) {
        int outsz = (o < 32) ? 32 : (o < 48) ? 16 : 48;
        int base  = (o < 32) ? 0  : (o < 48) ? 32 : 48;
        int r = o - base;
        double inv_scale = 64.0 / (double)outsz;
        double ks_inv    = (double)outsz * (1.0 / 64.0);
        double f = ((double)r + 0.5) * inv_scale - 0.5;
        int start = rowStart(o);
        double wv[16] = {};
        double wsum = 0.0;
        for (int k = 0; k < 16; k++) {
            int i = start + k;
            double w = (i < 64) ? keys_cubic_c(c_abs(f - (double)i) * ks_inv) : 0.0;
            wv[k] = w;
            wsum += w;
        }
        for (int k = 0; k < 16; k++)
            t.w[o][k] = (float)(wv[k] / wsum);
    }
    return t;
}

constexpr WTable WT = make_wtable();

// ---------------------------------------------------------------------------
// Full-window emitters (passW, R11-proven): v[64], weights as immediates.
// ---------------------------------------------------------------------------
template<int G, int K, bool Done>
struct Tap {
    static __device__ __forceinline__ float run(const float (&v)[64], float acc) {
        constexpr float wk = WT.w[G][K];
        constexpr int   st = rowStart(G);
        acc = fmaf(wk, v[st + K], acc);
        return Tap<G, K + 1, (K + 1 >= rowWidth(G))>::run(v, acc);
    }
};
template<int G, int K>
struct Tap<G, K, true> {
    static __device__ __forceinline__ float run(const float (&)[64], float acc) { return acc; }
};

template<int C, bool Done>
struct WCol {
    static __device__ __forceinline__ void run(const float (&v)[64],
                                               float* __restrict__ outp) {
        outp[(size_t)C * DIM] = Tap<C, 0, false>::run(v, 0.f);
        WCol<C + 1, (C + 1 >= NROWS_W)>::run(v, outp);
    }
};
template<int C>
struct WCol<C, true> {
    static __device__ __forceinline__ void run(const float (&)[64], float*) {}
};

// ---------------------------------------------------------------------------
// Banded emitters (passH, R14-proven): band of 40, in-block group split.
// ---------------------------------------------------------------------------
template<int G, int K, int BASE, bool Done>
struct TapB {
    static __device__ __forceinline__ float run(const float (&v)[BAND], float acc) {
        constexpr float wk = WT.w[G][K];
        constexpr int   ix = rowStart(G) - BASE + K;
        acc = fmaf(wk, v[ix], acc);
        return TapB<G, K + 1, BASE, (K + 1 >= rowWidth(G))>::run(v, acc);
    }
};
template<int G, int K, int BASE>
struct TapB<G, K, BASE, true> {
    static __device__ __forceinline__ float run(const float (&)[BAND], float acc) { return acc; }
};

template<int GBASE, int WS, int R, int Z, bool DoEmit>
struct HEmit {
    static __device__ __forceinline__ void run(const float (&v)[BAND],
                                               float* __restrict__ outp) {
        outp[(size_t)(R * WS) * DIM] = TapB<GBASE + R, 0, bandBase(Z), false>::run(v, 0.f);
    }
};
template<int GBASE, int WS, int R, int Z>
struct HEmit<GBASE, WS, R, Z, false> {
    static __device__ __forceinline__ void run(const float (&)[BAND], float*) {}
};

template<int GBASE, int RCNT, int WS, int R, int Z, bool Done>
struct HRowZ {
    static __device__ __forceinline__ void run(const float (&v)[BAND],
                                               float* __restrict__ outp) {
        HEmit<GBASE, WS, R, Z, inGroup(GBASE + R, Z)>::run(v, outp);
        HRowZ<GBASE, RCNT, WS, R + 1, Z, (R + 1 >= RCNT)>::run(v, outp);
    }
};
template<int GBASE, int RCNT, int WS, int R, int Z>
struct HRowZ<GBASE, RCNT, WS, R, Z, true> {
    static __device__ __forceinline__ void run(const float (&)[BAND], float*) {}
};

// ---------------------------------------------------------------------------
// Kernel 1 (FUSED): blocks [0,256)   = passW (row i = b>>2, 320-float d-chunk)
//                   blocks [256,1280) = identity-add for s3 tokens (DRAM-bound,
//                   independent of all prep -> overlaps passW's idle DRAM).
// ---------------------------------------------------------------------------
__global__ __launch_bounds__(320) void fused_passW_idadd_kernel(
        const float* __restrict__ weight,
        const float4* __restrict__ x,
        float4* __restrict__ out) {
    int b = blockIdx.x;
    if (b < 256) {
        // ---- passW: tmpW[i][c][d] = sum_k W[c][k] * weight[i][st_c+k][d] ----
        int i  = b >> 2;
        int d0 = (b & 3) * 320;
        int tid = threadIdx.x;

        float v[64];
        const float* wrow = weight + (size_t)(i * 64) * DIM + d0 + tid;
        #pragma unroll
        for (int j = 0; j < 64; j++)
            v[j] = wrow[(size_t)j * DIM];

        float* outp = g_tmpW + (size_t)i * NROWS_W * DIM + d0 + tid;
        WCol<0, false>::run(v, outp);
    } else {
        // ---- identity-add: out = x + weight_row, 4 tokens per block ----
        int u  = (b - 256) * TPB;            // 0..4092, token = 21504+u
        int d4 = threadIdx.x;
        const float4* w4 = (const float4*)weight;

        size_t base = (size_t)(21504 + u) * D4 + d4;
        #pragma unroll
        for (int j = 0; j < TPB; j++) {
            float4 a  = __ldcs(&x[base + (size_t)j * D4]);
            float4 pe = w4[(size_t)(u + j) * D4 + d4];
            float4 r;
            r.x = a.x + pe.x; r.y = a.y + pe.y;
            r.z = a.z + pe.z; r.w = a.w + pe.w;
            __stcs(&out[base + (size_t)j * D4], r);
        }
    }
}

// ---------------------------------------------------------------------------
// Kernel 2 (H-pass, R14-proven): 256 threads, in-block band split.
// ---------------------------------------------------------------------------
__global__ __launch_bounds__(256) void passH_kernel() {
    int c  = blockIdx.x;
    int d0 = blockIdx.y * 128;
    int tid = threadIdx.x & 127;
    int z   = threadIdx.x >> 7;

    float v[BAND];
    const float* src = g_tmpW + (size_t)c * DIM
                     + (size_t)(z * 24) * (NROWS_W * DIM) + d0 + tid;
    #pragma unroll
    for (int i = 0; i < BAND; i++)
        v[i] = src[(size_t)i * (NROWS_W * DIM)];

    if (c < 32) {
        float* outp = g_pe2d + (size_t)c * DIM + d0 + tid;
        if (z == 0) HRowZ<0, 32, 32, 0, 0, false>::run(v, outp);
        else        HRowZ<0, 32, 32, 0, 1, false>::run(v, outp);
    } else if (c < 48) {
        float* outp = g_pe2d + (size_t)(1024 + (c - 32)) * DIM + d0 + tid;
        if (z == 0) HRowZ<32, 16, 16, 0, 0, false>::run(v, outp);
        else        HRowZ<32, 16, 16, 0, 1, false>::run(v, outp);
    } else {
        float* outp = g_pe2d + (size_t)(1280 + (c - 48)) * DIM + d0 + tid;
        if (z == 0) HRowZ<48, 48, 48, 0, 0, false>::run(v, outp);
        else        HRowZ<48, 48, 48, 0, 1, false>::run(v, outp);
    }
}

// ---------------------------------------------------------------------------
// Kernel 3 (pe-add, R11-proven): out = x + pe2d + tw for s0/s1/s2 only.
// Block = 4 consecutive tokens x 320 threads; everything block-uniform.
// ---------------------------------------------------------------------------
__global__ __launch_bounds__(320) void add_kernel(const float4* __restrict__ x,
                                                  const float4* __restrict__ tw,
                                                  float4* __restrict__ out) {
    int t0 = blockIdx.x * TPB;
    int d4 = threadIdx.x;

    const float4* pe0;
    int frame;
    if (t0 < 8192) {                        // s0: t=8, 32x32
        frame = t0 >> 10;
        pe0 = (const float4*)g_pe2d + (size_t)(t0 & 1023) * D4;
    } else if (t0 < 12288) {                // s1: t=16, 16x16
        int u = t0 - 8192;
        frame = u >> 8;
        pe0 = (const float4*)g_pe2d + (size_t)(1024 + (u & 255)) * D4;
    } else {                                // s2: t=4, 48x48
        int u = t0 - 12288;
        frame = u / 2304;
        pe0 = (const float4*)g_pe2d + (size_t)(1280 + (u - frame * 2304)) * D4;
    }

    size_t base = (size_t)t0 * D4 + d4;

    float4 a[TPB], b[TPB];
    #pragma unroll
    for (int j = 0; j < TPB; j++) a[j] = __ldcs(&x[base + (size_t)j * D4]);
    #pragma unroll
    for (int j = 0; j < TPB; j++) b[j] = pe0[(size_t)j * D4 + d4];

    float4 t = tw[(size_t)frame * D4 + d4];

    #pragma unroll
    for (int j = 0; j < TPB; j++) {
        float4 r;
        r.x = a[j].x + b[j].x + t.x;
        r.y = a[j].y + b[j].y + t.y;
        r.z = a[j].z + b[j].z + t.z;
        r.w = a[j].w + b[j].w + t.w;
        __stcs(&out[base + (size_t)j * D4], r);
    }
}

// ---------------------------------------------------------------------------
extern "C" void kernel_launch(void* const* d_in, const int* in_sizes, int n_in,
                              void* d_out, int out_size) {
    const float* x      = (const float*)d_in[0];
    const float* weight = (const float*)d_in[1];
    const float* tw     = (const float*)d_in[2];
    float* out = (float*)d_out;

    fused_passW_idadd_kernel<<<256 + 1024, 320>>>(weight, (const float4*)x,
                                                  (float4*)out);
    passH_kernel<<<dim3(96, 10), 256>>>();
    add_kernel<<<21504 / TPB, 320>>>((const float4*)x, (const float4*)tw,
                                     (float4*)out);
}

// round 16
// speedup vs baseline: 1.0642x; 1.0348x over previous
#include <cuda_runtime.h>
#include <cuda_bf16.h>

// ---------------------------------------------------------------------------
// Static geometry:
//   s0: t=8,  32x32 -> tokens [0,8192)      pe2d rows [0,1024)
//   s1: t=16, 16x16 -> tokens [8192,12288)  pe2d rows [1024,1280)
//   s2: t=4,  48x48 -> tokens [12288,21504) pe2d rows [1280,3584)
//   s3: t=1,  64x64 -> tokens [21504,25600) pe = weight rows (independent of prep)
// ---------------------------------------------------------------------------
#define DIM      1280
#define D4       320
#define NROWS_W  96
#define PE_ROWS  3584
#define TOKENS   25600
#define TPB      4
#define BAND     40

__device__ float g_tmpW[64 * NROWS_W * DIM];   // [i][c][d]
__device__ float g_pe2d[PE_ROWS * DIM];

// --------------------------- tap-window geometry ---------------------------
__host__ __device__ constexpr int cdiv_ceil(int n, int d) {
    return (n >= 0) ? (n + d - 1) / d : -((-n) / d);
}
__host__ __device__ constexpr int iclamp(int v, int lo, int hi) {
    return v < lo ? lo : (v > hi ? hi : v);
}
__host__ __device__ constexpr int rowStart(int g) {
    return (g < 32) ? iclamp(2 * g - 3, 0, 56)
         : (g < 48) ? iclamp(4 * (g - 32) - 6, 0, 48)
                    : iclamp(cdiv_ceil(8 * (g - 48) - 15, 6), 0, 58);
}
__host__ __device__ constexpr int rowWidth(int g) {
    return (g < 32) ? 8 : (g < 48) ? 16 : 6;
}
__host__ __device__ constexpr bool inGroup(int g, int z) {
    return z == 0 ? (rowStart(g) <= 24) : (rowStart(g) >= 25);
}
__host__ __device__ constexpr int bandBase(int z) { return z * 24; }

// ------------------------ compile-time weight table ------------------------
constexpr double c_abs(double x) { return x < 0.0 ? -x : x; }
constexpr double keys_cubic_c(double x) {
    return (x >= 2.0) ? 0.0
         : (x >= 1.0) ? ((-0.5 * x + 2.5) * x - 4.0) * x + 2.0
                      : ((1.5 * x - 2.5) * x) * x + 1.0;
}

struct WTable { float w[NROWS_W][16]; };

constexpr WTable make_wtable() {
    WTable t{};
    for (int o = 0; o < NROWS_W; o++) {
        int outsz = (o < 32) ? 32 : (o < 48) ? 16 : 48;
        int base  = (o < 32) ? 0  : (o < 48) ? 32 : 48;
        int r = o - base;
        double inv_scale = 64.0 / (double)outsz;
        double ks_inv    = (double)outsz * (1.0 / 64.0);
        double f = ((double)r + 0.5) * inv_scale - 0.5;
        int start = rowStart(o);
        double wv[16] = {};
        double wsum = 0.0;
        for (int k = 0; k < 16; k++) {
            int i = start + k;
            double w = (i < 64) ? keys_cubic_c(c_abs(f - (double)i) * ks_inv) : 0.0;
            wv[k] = w;
            wsum += w;
        }
        for (int k = 0; k < 16; k++)
            t.w[o][k] = (float)(wv[k] / wsum);
    }
    return t;
}

constexpr WTable WT = make_wtable();

// -------------------- full-window emitters (passW, R11) --------------------
template<int G, int K, bool Done>
struct Tap {
    static __device__ __forceinline__ float run(const float (&v)[64], float acc) {
        constexpr float wk = WT.w[G][K];
        constexpr int   st = rowStart(G);
        acc = fmaf(wk, v[st + K], acc);
        return Tap<G, K + 1, (K + 1 >= rowWidth(G))>::run(v, acc);
    }
};
template<int G, int K>
struct Tap<G, K, true> {
    static __device__ __forceinline__ float run(const float (&)[64], float acc) { return acc; }
};

template<int C, bool Done>
struct WCol {
    static __device__ __forceinline__ void run(const float (&v)[64],
                                               float* __restrict__ outp) {
        outp[(size_t)C * DIM] = Tap<C, 0, false>::run(v, 0.f);
        WCol<C + 1, (C + 1 >= NROWS_W)>::run(v, outp);
    }
};
template<int C>
struct WCol<C, true> {
    static __device__ __forceinline__ void run(const float (&)[64], float*) {}
};

// --------------------- banded emitters (passH, R14) ------------------------
template<int G, int K, int BASE, bool Done>
struct TapB {
    static __device__ __forceinline__ float run(const float (&v)[BAND], float acc) {
        constexpr float wk = WT.w[G][K];
        constexpr int   ix = rowStart(G) - BASE + K;
        acc = fmaf(wk, v[ix], acc);
        return TapB<G, K + 1, BASE, (K + 1 >= rowWidth(G))>::run(v, acc);
    }
};
template<int G, int K, int BASE>
struct TapB<G, K, BASE, true> {
    static __device__ __forceinline__ float run(const float (&)[BAND], float acc) { return acc; }
};

template<int GBASE, int WS, int R, int Z, bool DoEmit>
struct HEmit {
    static __device__ __forceinline__ void run(const float (&v)[BAND],
                                               float* __restrict__ outp) {
        outp[(size_t)(R * WS) * DIM] = TapB<GBASE + R, 0, bandBase(Z), false>::run(v, 0.f);
    }
};
template<int GBASE, int WS, int R, int Z>
struct HEmit<GBASE, WS, R, Z, false> {
    static __device__ __forceinline__ void run(const float (&)[BAND], float*) {}
};

template<int GBASE, int RCNT, int WS, int R, int Z, bool Done>
struct HRowZ {
    static __device__ __forceinline__ void run(const float (&v)[BAND],
                                               float* __restrict__ outp) {
        HEmit<GBASE, WS, R, Z, inGroup(GBASE + R, Z)>::run(v, outp);
        HRowZ<GBASE, RCNT, WS, R + 1, Z, (R + 1 >= RCNT)>::run(v, outp);
    }
};
template<int GBASE, int RCNT, int WS, int R, int Z>
struct HRowZ<GBASE, RCNT, WS, R, Z, true> {
    static __device__ __forceinline__ void run(const float (&)[BAND], float*) {}
};

// ---------------------------------------------------------------------------
// K1: passW (R11-proven). Triggers PDL completion at entry so K2 can start
// flooding free SM slots with idadd work while passW's latency chains run.
// ---------------------------------------------------------------------------
__global__ __launch_bounds__(128) void passW_kernel(const float* __restrict__ weight) {
#if __CUDA_ARCH__ >= 900
    cudaTriggerProgrammaticLaunchCompletion();
#endif
    int i  = blockIdx.x;
    int d0 = blockIdx.y * 128;
    int tid = threadIdx.x;

    float v[64];
    const float* wrow = weight + (size_t)(i * 64) * DIM + d0 + tid;
    #pragma unroll
    for (int j = 0; j < 64; j++)
        v[j] = wrow[(size_t)j * DIM];

    float* outp = g_tmpW + (size_t)i * NROWS_W * DIM + d0 + tid;
    WCol<0, false>::run(v, outp);
}

// ---------------------------------------------------------------------------
// K2 (PDL secondary): blocks [0,1024)   = idadd (independent: runs immediately,
//                     overlapping passW via freed SM slots — pure linear stream:
//                     out[B+e] = x[B+e] + weight[W+e])
//                     blocks [1024,2064) = passH: gridDependencySynchronize()
//                     then R14 banded H-pass. Triggers early for K3.
// ---------------------------------------------------------------------------
__global__ __launch_bounds__(256) void fused_idadd_passH_kernel(
        const float4* __restrict__ x,
        const float*  __restrict__ weight,
        float4* __restrict__ out) {
#if __CUDA_ARCH__ >= 900
    cudaTriggerProgrammaticLaunchCompletion();
#endif
    int b = blockIdx.x;

    if (b < 1024) {
        // ---- identity add, 4 tokens = 1280 contiguous float4 per block ----
        int u = b * TPB;                                  // weight row offset
        const float4* w4 = (const float4*)weight;
        size_t xb = (size_t)(21504 + u) * D4;             // x/out base (float4)
        size_t wb = (size_t)u * D4;
        int tid = threadIdx.x;
        #pragma unroll
        for (int j = 0; j < 5; j++) {                     // 5*256 = 1280
            int e = j * 256 + tid;
            float4 a  = __ldcs(&x[xb + e]);
            float4 pe = w4[wb + e];
            float4 r;
            r.x = a.x + pe.x; r.y = a.y + pe.y;
            r.z = a.z + pe.z; r.w = a.w + pe.w;
            __stcs(&out[xb + e], r);
        }
        return;
    }

#if __CUDA_ARCH__ >= 900
    cudaGridDependencySynchronize();                      // tmpW must be complete
#endif
    // ---- passH (R14 banded, in-block group split) ----
    int bb = b - 1024;
    int c  = bb / 10;
    int d0 = (bb % 10) * 128;
    int tid = threadIdx.x & 127;
    int z   = threadIdx.x >> 7;

    float v[BAND];
    const float* src = g_tmpW + (size_t)c * DIM
                     + (size_t)(z * 24) * (NROWS_W * DIM) + d0 + tid;
    #pragma unroll
    for (int i = 0; i < BAND; i++)
        v[i] = src[(size_t)i * (NROWS_W * DIM)];

    if (c < 32) {
        float* outp = g_pe2d + (size_t)c * DIM + d0 + tid;
        if (z == 0) HRowZ<0, 32, 32, 0, 0, false>::run(v, outp);
        else        HRowZ<0, 32, 32, 0, 1, false>::run(v, outp);
    } else if (c < 48) {
        float* outp = g_pe2d + (size_t)(1024 + (c - 32)) * DIM + d0 + tid;
        if (z == 0) HRowZ<32, 16, 16, 0, 0, false>::run(v, outp);
        else        HRowZ<32, 16, 16, 0, 1, false>::run(v, outp);
    } else {
        float* outp = g_pe2d + (size_t)(1280 + (c - 48)) * DIM + d0 + tid;
        if (z == 0) HRowZ<48, 48, 48, 0, 0, false>::run(v, outp);
        else        HRowZ<48, 48, 48, 0, 1, false>::run(v, outp);
    }
}

// ---------------------------------------------------------------------------
// K3 (PDL secondary): pe-add for s0/s1/s2. PREAMBLE loads the x stream
// (independent of prep) BEFORE gridDependencySynchronize, so first-wave x
// reads overlap K2's tail; then pe2d/tw add + streaming store.
// ---------------------------------------------------------------------------
__global__ __launch_bounds__(320) void add_kernel(const float4* __restrict__ x,
                                                  const float4* __restrict__ tw,
                                                  float4* __restrict__ out) {
    int t0 = blockIdx.x * TPB;
    int d4 = threadIdx.x;

    size_t base = (size_t)t0 * D4 + d4;
    float4 a[TPB];
    #pragma unroll
    for (int j = 0; j < TPB; j++) a[j] = __ldcs(&x[base + (size_t)j * D4]);

#if __CUDA_ARCH__ >= 900
    cudaGridDependencySynchronize();                      // pe2d must be complete
#endif

    const float4* pe0;
    int frame;
    if (t0 < 8192) {                        // s0: t=8, 32x32
        frame = t0 >> 10;
        pe0 = (const float4*)g_pe2d + (size_t)(t0 & 1023) * D4;
    } else if (t0 < 12288) {                // s1: t=16, 16x16
        int u = t0 - 8192;
        frame = u >> 8;
        pe0 = (const float4*)g_pe2d + (size_t)(1024 + (u & 255)) * D4;
    } else {                                // s2: t=4, 48x48
        int u = t0 - 12288;
        frame = u / 2304;
        pe0 = (const float4*)g_pe2d + (size_t)(1280 + (u - frame * 2304)) * D4;
    }

    float4 bpe[TPB];
    #pragma unroll
    for (int j = 0; j < TPB; j++) bpe[j] = pe0[(size_t)j * D4 + d4];

    float4 t = tw[(size_t)frame * D4 + d4];

    #pragma unroll
    for (int j = 0; j < TPB; j++) {
        float4 r;
        r.x = a[j].x + bpe[j].x + t.x;
        r.y = a[j].y + bpe[j].y + t.y;
        r.z = a[j].z + bpe[j].z + t.z;
        r.w = a[j].w + bpe[j].w + t.w;
        __stcs(&out[base + (size_t)j * D4], r);
    }
}

// ---------------------------------------------------------------------------
static void launch_pdl(const void* func, dim3 grid, dim3 block,
                       void** args) {
    cudaLaunchConfig_t cfg = {};
    cfg.gridDim = grid;
    cfg.blockDim = block;
    cfg.dynamicSmemBytes = 0;
    cfg.stream = 0;                                    // legacy default stream
    cudaLaunchAttribute attr[1];
    attr[0].id = cudaLaunchAttributeProgrammaticStreamSerialization;
    attr[0].val.programmaticStreamSerializationAllowed = 1;
    cfg.attrs = attr;
    cfg.numAttrs = 1;
    cudaLaunchKernelExC(&cfg, func, args);
}

extern "C" void kernel_launch(void* const* d_in, const int* in_sizes, int n_in,
                              void* d_out, int out_size) {
    const float* x      = (const float*)d_in[0];
    const float* weight = (const float*)d_in[1];
    const float* tw     = (const float*)d_in[2];
    float* out = (float*)d_out;

    // K1: passW (primary; triggers early)
    passW_kernel<<<dim3(64, 10), 128>>>(weight);

    // K2: idadd (independent) + passH (gridDepSync), PDL-overlapped with K1
    {
        const float4* xa = (const float4*)x;
        float4* oa = (float4*)out;
        void* args[] = { (void*)&xa, (void*)&weight, (void*)&oa };
        launch_pdl((const void*)fused_idadd_passH_kernel,
                   dim3(1024 + 960), dim3(256), args);
    }

    // K3: pe-add with x-preamble, PDL-overlapped with K2
    {
        const float4* xa = (const float4*)x;
        const float4* twa = (const float4*)tw;
        float4* oa = (float4*)out;
        void* args[] = { (void*)&xa, (void*)&twa, (void*)&oa };
        launch_pdl((const void*)add_kernel, dim3(21504 / TPB), dim3(320), args);
    }
}